// round 12
// baseline (speedup 1.0000x reference)
#include <cuda_runtime.h>
#include <cuda_bf16.h>
#include <cstdint>

// Fused conv3x3(SAME)+bias+min_k+tanh(tanh) via warp-level bf16 mma.sync.
// Warp-desynchronized: per-warp rotated tap/kc order + split arrive/sync
// barriers so ldsm bursts of some warps overlap mma of others.
// N=16, C=64, H=W=256, K=64. x f32 NCHW, w f32 [K,C,3,3], b f32 [64].

__device__ __nv_bfloat16 g_wtb[9 * 64 * 64];              // [rs][k][c]

__device__ __forceinline__ uint32_t smem_u32(const void* p) {
    uint32_t a;
    asm("{ .reg .u64 t; cvta.to.shared.u64 t, %1; cvt.u32.u64 %0, t; }" : "=r"(a) : "l"(p));
    return a;
}
__device__ __forceinline__ uint32_t pack_bf16x2(float lo, float hi) {
    uint32_t r;
    asm("cvt.rn.bf16x2.f32 %0, %1, %2;" : "=r"(r) : "f"(hi), "f"(lo));
    return r;
}
#define LDSM_X4(r, addr)                                                        \
    asm volatile("ldmatrix.sync.aligned.m8n8.x4.shared.b16 {%0,%1,%2,%3}, [%4];" \
                 : "=r"((r)[0]), "=r"((r)[1]), "=r"((r)[2]), "=r"((r)[3]) : "r"(addr))
#define BAR_SYNC(id)   asm volatile("bar.sync %0, 512;"   :: "r"(id) : "memory")
#define BAR_ARRIVE(id) asm volatile("bar.arrive %0, 512;" :: "r"(id) : "memory")

__device__ __forceinline__ void mma_bf16(float* d, const uint32_t* a, const uint32_t* b) {
    asm volatile(
        "mma.sync.aligned.m16n8k16.row.col.f32.bf16.bf16.f32 "
        "{%0,%1,%2,%3}, {%4,%5,%6,%7}, {%8,%9}, {%0,%1,%2,%3};"
        : "+f"(d[0]), "+f"(d[1]), "+f"(d[2]), "+f"(d[3])
        : "r"(a[0]), "r"(a[1]), "r"(a[2]), "r"(a[3]), "r"(b[0]), "r"(b[1]));
}

// ---------------- prep: w [K,C,3,3] f32 -> [rs][k][c] bf16 -----------------
__global__ void prep_w_kernel(const float* __restrict__ w) {
    int i = blockIdx.x * 256 + threadIdx.x;     // rs*4096 + k*64 + c
    if (i >= 9 * 64 * 64) return;
    int rs = i >> 12, rem = i & 4095, k = rem >> 6, c = rem & 63;
    g_wtb[i] = __float2bfloat16(w[(size_t)(k * 64 + c) * 9 + rs]);
}

// ---------------- main kernel ----------------------------------------------
#define PXS      144
#define AROW     (260 * PXS)               // 37440
#define SM_A     0
#define SM_B     (4 * AROW)                // 149760
#define SM_BIAS  (SM_B + 9 * 8192)         // 223488
#define SM_TOTAL (SM_BIAS + 256)           // 223744

__global__ void __launch_bounds__(512, 1)
conv_mma_kernel(const float* __restrict__ x,
                const float* __restrict__ bias, float* __restrict__ out) {
    extern __shared__ char smem[];
    const uint32_t sb = smem_u32(smem);
    const int tid = threadIdx.x, wid = tid >> 5, lane = tid & 31;
    const int cq = lane & 3, lrow = lane >> 2;

    const int n  = blockIdx.y;
    const int hs = blockIdx.x * 8;
    const float* xn = x + (size_t)n * 64 * 65536;

    // ---- stage B (swizzled) + bias, once ----
    for (int i = tid; i < 9 * 64 * 8; i += 512) {
        int rs = i >> 9, rem = i & 511, k = rem >> 3, c16 = rem & 7;
        uint4 v = *reinterpret_cast<const uint4*>(g_wtb + rs * 4096 + k * 64 + c16 * 8);
        uint32_t off = (uint32_t)(k * 128 + c16 * 16);
        off ^= (off >> 3) & 0x70;
        *reinterpret_cast<uint4*>(smem + SM_B + rs * 8192 + off) = v;
    }
    if (tid < 64) ((float*)(smem + SM_BIAS))[tid] = bias[tid];

    // full-row staging helper (prologue only)
    auto stage_row_c = [&](int hh, int c0) {
        const int slot = (hh + 4) & 3;
        const bool hok = (unsigned)hh < 256u;
        const float* src = xn + (size_t)c0 * 65536 + (size_t)(hok ? hh : 0) * 256;
        #pragma unroll
        for (int chunk = 0; chunk < 9; ++chunk) {
            int px = chunk * 32 - 1 + lane;
            bool pok = hok && (unsigned)px < 256u;
            float v[8];
            #pragma unroll
            for (int j = 0; j < 8; ++j)
                v[j] = pok ? src[j * 65536 + px] : 0.0f;
            if (px <= 258) {
                uint4 pk;
                pk.x = pack_bf16x2(v[0], v[1]);
                pk.y = pack_bf16x2(v[2], v[3]);
                pk.z = pack_bf16x2(v[4], v[5]);
                pk.w = pack_bf16x2(v[6], v[7]);
                *reinterpret_cast<uint4*>(smem + SM_A + slot * AROW + (px + 1) * PXS + c0 * 2) = pk;
            }
        }
    };

    // initial window: rows hs-1 .. hs+2 (16 warps x 2 tasks = 4 rows x 8 cgroups)
    #pragma unroll
    for (int q = 0; q < 2; ++q)
        stage_row_c(hs - 1 + (wid & 3), ((wid >> 2) + q * 4) * 8);
    __syncthreads();

    // compute mapping: 16 warps -> 2 rows x 256 px per iteration
    const int hoff    = wid & 1;
    const int pxwbase = (wid >> 1) * 32;
    const uint32_t aLane = (uint32_t)((lane & 15) * PXS + ((lane >> 4) << 4));
    const int rowb = (lane & 7) + ((lane >> 4) << 3);
    const int colb = ((lane >> 3) & 1) << 4;
    const float* bs = (const float*)(smem + SM_BIAS);

    const bool grpA = (wid < 8);
    const int  swid = wid % 3;               // per-warp s rotation

    for (int hp = hs; hp < hs + 8; hp += 2) {
        const int hrow = hp + hoff;
        const bool do_stage = (hp + 2 < hs + 8);

        const int  srow  = hp + (grpA ? 3 : 4);
        const int  sc0   = (grpA ? wid : wid - 8) * 8;
        const bool rowok = (unsigned)srow < 256u;
        const int  sslot = (srow + 4) & 3;
        const float* ssrc = xn + (size_t)sc0 * 65536 + (size_t)(rowok ? srow : 0) * 256;

        auto stage_chunks = [&](int cbase, int cnt) {
            if (!do_stage) return;
            float v[3][8];
            #pragma unroll
            for (int cc = 0; cc < 3; ++cc) {
                if (cc >= cnt) continue;
                int px = (cbase + cc) * 32 - 1 + lane;
                bool pok = rowok && (unsigned)px < 256u;
                #pragma unroll
                for (int j = 0; j < 8; ++j)
                    v[cc][j] = pok ? ssrc[j * 65536 + px] : 0.0f;
            }
            #pragma unroll
            for (int cc = 0; cc < 3; ++cc) {
                if (cc >= cnt) continue;
                int px = (cbase + cc) * 32 - 1 + lane;
                if (px <= 258) {
                    uint4 pk;
                    pk.x = pack_bf16x2(v[cc][0], v[cc][1]);
                    pk.y = pack_bf16x2(v[cc][2], v[cc][3]);
                    pk.z = pack_bf16x2(v[cc][4], v[cc][5]);
                    pk.w = pack_bf16x2(v[cc][6], v[cc][7]);
                    *reinterpret_cast<uint4*>(smem + SM_A + sslot * AROW + (px + 1) * PXS + sc0 * 2) = pk;
                }
            }
        };

        // acc init = bias (bias add folded into the GEMM)
        float acc[2][8][4];
        #pragma unroll
        for (int mf = 0; mf < 2; ++mf)
            #pragma unroll
            for (int nf = 0; nf < 8; ++nf)
                #pragma unroll
                for (int j = 0; j < 4; ++j)
                    acc[mf][nf][j] = bs[nf * 8 + 2 * cq + (j & 1)];

        #pragma unroll
        for (int t = 0; t < 9; ++t) {
            const int r = t / 3;
            int s_eff = (t % 3) + swid; if (s_eff >= 3) s_eff -= 3;   // warp-rotated
            const int tap = r * 3 + s_eff;
            const int slot = (hrow + 3 + r) & 3;                      // row hrow-1+r
            const uint32_t aBase = sb + SM_A + slot * AROW + (pxwbase + s_eff) * PXS + aLane;
            const uint32_t bBase = sb + SM_B + tap * 8192;
            #pragma unroll
            for (int kc = 0; kc < 4; ++kc) {
                const int kce = (kc + wid) & 3;                       // warp-rotated
                uint32_t a[2][4];
                #pragma unroll
                for (int mf = 0; mf < 2; ++mf)
                    LDSM_X4(a[mf], aBase + mf * (16 * PXS) + kce * 32);
                uint32_t bb[16];
                #pragma unroll
                for (int nb = 0; nb < 4; ++nb) {
                    uint32_t off = (uint32_t)((rowb + nb * 16) * 128 + colb + kce * 32);
                    off ^= (off >> 3) & 0x70;
                    LDSM_X4(bb + nb * 4, bBase + off);
                }
                #pragma unroll
                for (int nb = 0; nb < 4; ++nb)
                    #pragma unroll
                    for (int mf = 0; mf < 2; ++mf) {
                        mma_bf16(acc[mf][2 * nb + 0], a[mf], bb + nb * 4 + 0);
                        mma_bf16(acc[mf][2 * nb + 1], a[mf], bb + nb * 4 + 2);
                    }
            }

            // ---- overlap hooks: only stagers block; others arrive and go on --
            if (t == 2) { if (grpA) BAR_SYNC(1); else BAR_ARRIVE(1); }
            if (t == 5) { if (grpA) BAR_ARRIVE(2); else BAR_SYNC(2); }
            if (grpA) {                              // stage row hp+3, steps 3..8
                if (t == 3) stage_chunks(0, 2);
                if (t == 4) stage_chunks(2, 2);
                if (t == 5) stage_chunks(4, 2);
                if (t == 6) stage_chunks(6, 1);
                if (t == 7) stage_chunks(7, 1);
                if (t == 8) stage_chunks(8, 1);
            } else {                                 // stage row hp+4, steps 6..8
                if (t == 6) stage_chunks(0, 3);
                if (t == 7) stage_chunks(3, 3);
                if (t == 8) stage_chunks(6, 3);
            }
        }

        // ---- epilogue: min over 64 k (bias already in acc) + tanh + store ----
        #pragma unroll
        for (int mf = 0; mf < 2; ++mf) {
            #pragma unroll
            for (int half = 0; half < 2; ++half) {
                float m = fminf(acc[mf][0][half * 2 + 0], acc[mf][0][half * 2 + 1]);
                #pragma unroll
                for (int nf = 1; nf < 8; ++nf)
                    m = fminf(m, fminf(acc[mf][nf][half * 2 + 0],
                                       acc[mf][nf][half * 2 + 1]));
                m = fminf(m, __shfl_xor_sync(0xFFFFFFFFu, m, 1));
                m = fminf(m, __shfl_xor_sync(0xFFFFFFFFu, m, 2));
                if (cq == 0) {
                    int px = pxwbase + mf * 16 + half * 8 + lrow;
                    out[(size_t)n * 65536 + (size_t)hrow * 256 + px] = tanhf(tanhf(m));
                }
            }
        }

        __syncthreads();   // staged rows visible; all reads done before next writes
    }
}

// ---------------- launch ---------------------------------------------------
extern "C" void kernel_launch(void* const* d_in, const int* in_sizes, int n_in,
                              void* d_out, int out_size) {
    const float* x = (const float*)d_in[0];
    const float* w = (const float*)d_in[1];
    const float* b = (const float*)d_in[2];
    float* out = (float*)d_out;

    cudaFuncSetAttribute(conv_mma_kernel,
                         cudaFuncAttributeMaxDynamicSharedMemorySize, SM_TOTAL);

    prep_w_kernel<<<(9 * 64 * 64 + 255) / 256, 256>>>(w);

    dim3 grid(32, 16);   // (h-strips of 8, n)
    conv_mma_kernel<<<grid, 512, SM_TOTAL>>>(x, b, out);
}

// round 13
// speedup vs baseline: 1.0794x; 1.0794x over previous
#include <cuda_runtime.h>
#include <cuda_bf16.h>
#include <cstdint>

// Fused conv3x3(SAME)+bias+min_k+tanh(tanh) via warp-level bf16 mma.sync.
// 8 fat warps (M=64/warp, 256 threads): big reg budget -> ptxas pipelines
// ldsm under mma; B-fragment reuse x4 halves crossbar traffic.
// N=16, C=64, H=W=256, K=64. x f32 NCHW, w f32 [K,C,3,3], b f32 [64].

__device__ __nv_bfloat16 g_wtb[9 * 64 * 64];              // [rs][k][c]

__device__ __forceinline__ uint32_t smem_u32(const void* p) {
    uint32_t a;
    asm("{ .reg .u64 t; cvta.to.shared.u64 t, %1; cvt.u32.u64 %0, t; }" : "=r"(a) : "l"(p));
    return a;
}
__device__ __forceinline__ uint32_t pack_bf16x2(float lo, float hi) {
    uint32_t r;
    asm("cvt.rn.bf16x2.f32 %0, %1, %2;" : "=r"(r) : "f"(hi), "f"(lo));
    return r;
}
#define LDSM_X4(r, addr)                                                        \
    asm volatile("ldmatrix.sync.aligned.m8n8.x4.shared.b16 {%0,%1,%2,%3}, [%4];" \
                 : "=r"((r)[0]), "=r"((r)[1]), "=r"((r)[2]), "=r"((r)[3]) : "r"(addr))
#define BAR_SYNC(id) asm volatile("bar.sync %0, 256;" :: "r"(id) : "memory")

__device__ __forceinline__ void mma_bf16(float* d, const uint32_t* a, const uint32_t* b) {
    asm volatile(
        "mma.sync.aligned.m16n8k16.row.col.f32.bf16.bf16.f32 "
        "{%0,%1,%2,%3}, {%4,%5,%6,%7}, {%8,%9}, {%0,%1,%2,%3};"
        : "+f"(d[0]), "+f"(d[1]), "+f"(d[2]), "+f"(d[3])
        : "r"(a[0]), "r"(a[1]), "r"(a[2]), "r"(a[3]), "r"(b[0]), "r"(b[1]));
}

// ---------------- prep: w [K,C,3,3] f32 -> [rs][k][c] bf16 -----------------
__global__ void prep_w_kernel(const float* __restrict__ w) {
    int i = blockIdx.x * 256 + threadIdx.x;     // rs*4096 + k*64 + c
    if (i >= 9 * 64 * 64) return;
    int rs = i >> 12, rem = i & 4095, k = rem >> 6, c = rem & 63;
    g_wtb[i] = __float2bfloat16(w[(size_t)(k * 64 + c) * 9 + rs]);
}

// ---------------- main kernel ----------------------------------------------
#define PXS      144
#define AROW     (260 * PXS)               // 37440
#define SM_A     0
#define SM_B     (4 * AROW)                // 149760
#define SM_BIAS  (SM_B + 9 * 8192)         // 223488
#define SM_TOTAL (SM_BIAS + 256)           // 223744

__global__ void __launch_bounds__(256, 1)
conv_mma_kernel(const float* __restrict__ x,
                const float* __restrict__ bias, float* __restrict__ out) {
    extern __shared__ char smem[];
    const uint32_t sb = smem_u32(smem);
    const int tid = threadIdx.x, wid = tid >> 5, lane = tid & 31;
    const int cq = lane & 3, lrow = lane >> 2;

    const int n  = blockIdx.y;
    const int hs = blockIdx.x * 8;
    const float* xn = x + (size_t)n * 64 * 65536;

    // ---- stage B (swizzled) + bias, once ----
    for (int i = tid; i < 9 * 64 * 8; i += 256) {
        int rs = i >> 9, rem = i & 511, k = rem >> 3, c16 = rem & 7;
        uint4 v = *reinterpret_cast<const uint4*>(g_wtb + rs * 4096 + k * 64 + c16 * 8);
        uint32_t off = (uint32_t)(k * 128 + c16 * 16);
        off ^= (off >> 3) & 0x70;
        *reinterpret_cast<uint4*>(smem + SM_B + rs * 8192 + off) = v;
    }
    if (tid < 64) ((float*)(smem + SM_BIAS))[tid] = bias[tid];

    // full-row staging of one 8-channel group (prologue only)
    auto stage_row_c = [&](int hh, int c0) {
        const int slot = (hh + 4) & 3;
        const bool hok = (unsigned)hh < 256u;
        const float* src = xn + (size_t)c0 * 65536 + (size_t)(hok ? hh : 0) * 256;
        #pragma unroll
        for (int chunk = 0; chunk < 9; ++chunk) {
            int px = chunk * 32 - 1 + lane;
            bool pok = hok && (unsigned)px < 256u;
            float v[8];
            #pragma unroll
            for (int j = 0; j < 8; ++j)
                v[j] = pok ? src[j * 65536 + px] : 0.0f;
            if (px <= 258) {
                uint4 pk;
                pk.x = pack_bf16x2(v[0], v[1]);
                pk.y = pack_bf16x2(v[2], v[3]);
                pk.z = pack_bf16x2(v[4], v[5]);
                pk.w = pack_bf16x2(v[6], v[7]);
                *reinterpret_cast<uint4*>(smem + SM_A + slot * AROW + (px + 1) * PXS + c0 * 2) = pk;
            }
        }
    };

    // initial window: rows hs-1..hs+2; 8 warps x 4 tasks = 4 rows x 8 cgroups
    #pragma unroll
    for (int q = 0; q < 4; ++q)
        stage_row_c(hs - 1 + (wid & 3), ((wid >> 2) + q * 2) * 8);
    __syncthreads();

    // compute mapping: 8 warps -> 2 rows x 256 px per iteration (M=64/warp)
    const int hoff    = wid & 1;
    const int pxwbase = (wid >> 1) * 64;
    const uint32_t aLane = (uint32_t)((lane & 15) * PXS + ((lane >> 4) << 4));
    const int rowb = (lane & 7) + ((lane >> 4) << 3);
    const int colb = ((lane >> 3) & 1) << 4;
    const float* bs = (const float*)(smem + SM_BIAS);

    const int sc0 = wid * 8;                 // each warp stages cgroup wid of both rows

    for (int hp = hs; hp < hs + 8; hp += 2) {
        const int hrow = hp + hoff;
        const bool do_stage = (hp + 2 < hs + 8);
        const int rowA = hp + 3, rowB = hp + 4;

        auto stage_chunks = [&](int srow, int cbase, int cnt) {
            if (!do_stage) return;
            const bool rowok = (unsigned)srow < 256u;
            const int sslot = (srow + 4) & 3;
            const float* ssrc = xn + (size_t)sc0 * 65536 + (size_t)(rowok ? srow : 0) * 256;
            float v[3][8];
            #pragma unroll
            for (int cc = 0; cc < 3; ++cc) {
                if (cc >= cnt) continue;
                int px = (cbase + cc) * 32 - 1 + lane;
                bool pok = rowok && (unsigned)px < 256u;
                #pragma unroll
                for (int j = 0; j < 8; ++j)
                    v[cc][j] = pok ? ssrc[j * 65536 + px] : 0.0f;
            }
            #pragma unroll
            for (int cc = 0; cc < 3; ++cc) {
                if (cc >= cnt) continue;
                int px = (cbase + cc) * 32 - 1 + lane;
                if (px <= 258) {
                    uint4 pk;
                    pk.x = pack_bf16x2(v[cc][0], v[cc][1]);
                    pk.y = pack_bf16x2(v[cc][2], v[cc][3]);
                    pk.z = pack_bf16x2(v[cc][4], v[cc][5]);
                    pk.w = pack_bf16x2(v[cc][6], v[cc][7]);
                    *reinterpret_cast<uint4*>(smem + SM_A + sslot * AROW + (px + 1) * PXS + sc0 * 2) = pk;
                }
            }
        };

        // acc init = bias (bias add folded into the GEMM)
        float acc[4][8][4];
        #pragma unroll
        for (int mf = 0; mf < 4; ++mf)
            #pragma unroll
            for (int nf = 0; nf < 8; ++nf)
                #pragma unroll
                for (int j = 0; j < 4; ++j)
                    acc[mf][nf][j] = bs[nf * 8 + 2 * cq + (j & 1)];

        #pragma unroll
        for (int t = 0; t < 9; ++t) {
            const int r = t / 3, s = t % 3;
            const int slot = (hrow + 3 + r) & 3;          // row hrow-1+r
            const uint32_t aBase = sb + SM_A + slot * AROW + (pxwbase + s) * PXS + aLane;
            const uint32_t bBase = sb + SM_B + t * 8192;
            #pragma unroll
            for (int kc = 0; kc < 4; ++kc) {
                uint32_t a[4][4];
                #pragma unroll
                for (int mf = 0; mf < 4; ++mf)
                    LDSM_X4(a[mf], aBase + mf * (16 * PXS) + kc * 32);
                uint32_t bb[16];
                #pragma unroll
                for (int nb = 0; nb < 4; ++nb) {
                    uint32_t off = (uint32_t)((rowb + nb * 16) * 128 + colb + kc * 32);
                    off ^= (off >> 3) & 0x70;
                    LDSM_X4(bb + nb * 4, bBase + off);
                }
                #pragma unroll
                for (int nb = 0; nb < 4; ++nb)
                    #pragma unroll
                    for (int mf = 0; mf < 4; ++mf) {
                        mma_bf16(acc[mf][2 * nb + 0], a[mf], bb + nb * 4 + 0);
                        mma_bf16(acc[mf][2 * nb + 1], a[mf], bb + nb * 4 + 2);
                    }
            }

            // ---- overlap hooks: stage rows hp+3/hp+4 into freed slots ----
            if (t == 2) BAR_SYNC(1);                 // slot(row hp-1) now dead
            if (t == 5) BAR_SYNC(2);                 // slot(row hp)   now dead
            if (t == 3) stage_chunks(rowA, 0, 2);
            if (t == 4) stage_chunks(rowA, 2, 2);
            if (t == 5) stage_chunks(rowA, 4, 2);
            if (t == 6) { stage_chunks(rowA, 6, 1); stage_chunks(rowB, 0, 3); }
            if (t == 7) { stage_chunks(rowA, 7, 1); stage_chunks(rowB, 3, 3); }
            if (t == 8) { stage_chunks(rowA, 8, 1); stage_chunks(rowB, 6, 3); }
        }

        // ---- epilogue: min over 64 k (bias already in acc) + tanh + store ----
        #pragma unroll
        for (int mf = 0; mf < 4; ++mf) {
            #pragma unroll
            for (int half = 0; half < 2; ++half) {
                float m = fminf(acc[mf][0][half * 2 + 0], acc[mf][0][half * 2 + 1]);
                #pragma unroll
                for (int nf = 1; nf < 8; ++nf)
                    m = fminf(m, fminf(acc[mf][nf][half * 2 + 0],
                                       acc[mf][nf][half * 2 + 1]));
                m = fminf(m, __shfl_xor_sync(0xFFFFFFFFu, m, 1));
                m = fminf(m, __shfl_xor_sync(0xFFFFFFFFu, m, 2));
                if (cq == 0) {
                    int px = pxwbase + mf * 16 + half * 8 + lrow;
                    out[(size_t)n * 65536 + (size_t)hrow * 256 + px] = tanhf(tanhf(m));
                }
            }
        }

        __syncthreads();   // staged rows visible; all reads done before next writes
    }
}

// ---------------- launch ---------------------------------------------------
extern "C" void kernel_launch(void* const* d_in, const int* in_sizes, int n_in,
                              void* d_out, int out_size) {
    const float* x = (const float*)d_in[0];
    const float* w = (const float*)d_in[1];
    const float* b = (const float*)d_in[2];
    float* out = (float*)d_out;

    cudaFuncSetAttribute(conv_mma_kernel,
                         cudaFuncAttributeMaxDynamicSharedMemorySize, SM_TOTAL);

    prep_w_kernel<<<(9 * 64 * 64 + 255) / 256, 256>>>(w);

    dim3 grid(32, 16);   // (h-strips of 8, n)
    conv_mma_kernel<<<grid, 256, SM_TOTAL>>>(x, b, out);
}

// round 17
// speedup vs baseline: 1.1641x; 1.0785x over previous
#include <cuda_runtime.h>
#include <cuda_bf16.h>
#include <cstdint>

// Fused conv3x3(SAME)+bias+min_k+tanh(tanh) via warp-level bf16 mma.sync.
// R11 base + 4-row strips (wave balance: 1024 CTAs = 6.92 waves) + static
// per-warp-group kc direction divergence (anti-phase ldsm bursts).
// N=16, C=64, H=W=256, K=64. x f32 NCHW, w f32 [K,C,3,3], b f32 [64].

__device__ __nv_bfloat16 g_wtb[9 * 64 * 64];              // [rs][k][c]

__device__ __forceinline__ uint32_t smem_u32(const void* p) {
    uint32_t a;
    asm("{ .reg .u64 t; cvta.to.shared.u64 t, %1; cvt.u32.u64 %0, t; }" : "=r"(a) : "l"(p));
    return a;
}
__device__ __forceinline__ uint32_t pack_bf16x2(float lo, float hi) {
    uint32_t r;
    asm("cvt.rn.bf16x2.f32 %0, %1, %2;" : "=r"(r) : "f"(hi), "f"(lo));
    return r;
}
#define LDSM_X4(r, addr)                                                        \
    asm volatile("ldmatrix.sync.aligned.m8n8.x4.shared.b16 {%0,%1,%2,%3}, [%4];" \
                 : "=r"((r)[0]), "=r"((r)[1]), "=r"((r)[2]), "=r"((r)[3]) : "r"(addr))
#define BAR_SYNC(id) asm volatile("bar.sync %0, 512;" :: "r"(id) : "memory")

__device__ __forceinline__ void mma_bf16(float* d, const uint32_t* a, const uint32_t* b) {
    asm volatile(
        "mma.sync.aligned.m16n8k16.row.col.f32.bf16.bf16.f32 "
        "{%0,%1,%2,%3}, {%4,%5,%6,%7}, {%8,%9}, {%0,%1,%2,%3};"
        : "+f"(d[0]), "+f"(d[1]), "+f"(d[2]), "+f"(d[3])
        : "r"(a[0]), "r"(a[1]), "r"(a[2]), "r"(a[3]), "r"(b[0]), "r"(b[1]));
}

// one tap's 4 kc-steps, direction chosen at compile time per warp group
template <bool FWD>
__device__ __forceinline__ void tap_mma(float acc[2][8][4], uint32_t aBase,
                                        uint32_t bBase, int rowb, int colb) {
    #pragma unroll
    for (int i = 0; i < 4; ++i) {
        const int kc = FWD ? i : 3 - i;
        uint32_t a[2][4];
        #pragma unroll
        for (int mf = 0; mf < 2; ++mf)
            LDSM_X4(a[mf], aBase + mf * (16 * 144) + kc * 32);
        uint32_t bb[16];
        #pragma unroll
        for (int nb = 0; nb < 4; ++nb) {
            uint32_t off = (uint32_t)((rowb + nb * 16) * 128 + colb + kc * 32);
            off ^= (off >> 3) & 0x70;
            LDSM_X4(bb + nb * 4, bBase + off);
        }
        #pragma unroll
        for (int nb = 0; nb < 4; ++nb)
            #pragma unroll
            for (int mf = 0; mf < 2; ++mf) {
                mma_bf16(acc[mf][2 * nb + 0], a[mf], bb + nb * 4 + 0);
                mma_bf16(acc[mf][2 * nb + 1], a[mf], bb + nb * 4 + 2);
            }
    }
}

// ---------------- prep: w [K,C,3,3] f32 -> [rs][k][c] bf16 -----------------
__global__ void prep_w_kernel(const float* __restrict__ w) {
    int i = blockIdx.x * 256 + threadIdx.x;     // rs*4096 + k*64 + c
    if (i >= 9 * 64 * 64) return;
    int rs = i >> 12, rem = i & 4095, k = rem >> 6, c = rem & 63;
    g_wtb[i] = __float2bfloat16(w[(size_t)(k * 64 + c) * 9 + rs]);
}

// ---------------- main kernel ----------------------------------------------
#define PXS      144
#define AROW     (260 * PXS)               // 37440
#define SM_A     0
#define SM_B     (4 * AROW)                // 149760
#define SM_BIAS  (SM_B + 9 * 8192)         // 223488
#define SM_TOTAL (SM_BIAS + 256)           // 223744

__global__ void __launch_bounds__(512, 1)
conv_mma_kernel(const float* __restrict__ x,
                const float* __restrict__ bias, float* __restrict__ out) {
    extern __shared__ char smem[];
    const uint32_t sb = smem_u32(smem);
    const int tid = threadIdx.x, wid = tid >> 5, lane = tid & 31;
    const int cq = lane & 3, lrow = lane >> 2;

    const int n  = blockIdx.y;
    const int hs = blockIdx.x * 4;          // 4-row strip
    const float* xn = x + (size_t)n * 64 * 65536;

    // ---- stage B (swizzled) + bias, once ----
    for (int i = tid; i < 9 * 64 * 8; i += 512) {
        int rs = i >> 9, rem = i & 511, k = rem >> 3, c16 = rem & 7;
        uint4 v = *reinterpret_cast<const uint4*>(g_wtb + rs * 4096 + k * 64 + c16 * 8);
        uint32_t off = (uint32_t)(k * 128 + c16 * 16);
        off ^= (off >> 3) & 0x70;
        *reinterpret_cast<uint4*>(smem + SM_B + rs * 8192 + off) = v;
    }
    if (tid < 64) ((float*)(smem + SM_BIAS))[tid] = bias[tid];

    // full-row staging helper (prologue only)
    auto stage_row_c = [&](int hh, int c0) {
        const int slot = (hh + 4) & 3;
        const bool hok = (unsigned)hh < 256u;
        const float* src = xn + (size_t)c0 * 65536 + (size_t)(hok ? hh : 0) * 256;
        #pragma unroll
        for (int chunk = 0; chunk < 9; ++chunk) {
            int px = chunk * 32 - 1 + lane;
            bool pok = hok && (unsigned)px < 256u;
            float v[8];
            #pragma unroll
            for (int j = 0; j < 8; ++j)
                v[j] = pok ? src[j * 65536 + px] : 0.0f;
            if (px <= 258) {
                uint4 pk;
                pk.x = pack_bf16x2(v[0], v[1]);
                pk.y = pack_bf16x2(v[2], v[3]);
                pk.z = pack_bf16x2(v[4], v[5]);
                pk.w = pack_bf16x2(v[6], v[7]);
                *reinterpret_cast<uint4*>(smem + SM_A + slot * AROW + (px + 1) * PXS + c0 * 2) = pk;
            }
        }
    };

    // initial window: rows hs-1 .. hs+2 (16 warps x 2 tasks = 4 rows x 8 cgroups)
    #pragma unroll
    for (int q = 0; q < 2; ++q)
        stage_row_c(hs - 1 + (wid & 3), ((wid >> 2) + q * 4) * 8);
    __syncthreads();

    // compute mapping: 16 warps -> 2 rows x 256 px per iteration
    const int hoff    = wid & 1;
    const int pxwbase = (wid >> 1) * 32;
    const uint32_t aLane = (uint32_t)((lane & 15) * PXS + ((lane >> 4) << 4));
    const int rowb = (lane & 7) + ((lane >> 4) << 3);
    const int colb = ((lane >> 3) & 1) << 4;
    const float* bs = (const float*)(smem + SM_BIAS);

    const bool grpA = (wid < 8);

    for (int hp = hs; hp < hs + 4; hp += 2) {
        const int hrow = hp + hoff;
        const bool do_stage = (hp + 2 < hs + 4);

        const int  srow  = hp + (grpA ? 3 : 4);
        const int  sc0   = (grpA ? wid : wid - 8) * 8;
        const bool rowok = (unsigned)srow < 256u;
        const int  sslot = (srow + 4) & 3;
        const float* ssrc = xn + (size_t)sc0 * 65536 + (size_t)(rowok ? srow : 0) * 256;

        auto stage_chunks = [&](int cbase, int cnt) {
            if (!do_stage) return;
            float v[3][8];
            #pragma unroll
            for (int cc = 0; cc < 3; ++cc) {
                if (cc >= cnt) continue;
                int px = (cbase + cc) * 32 - 1 + lane;
                bool pok = rowok && (unsigned)px < 256u;
                #pragma unroll
                for (int j = 0; j < 8; ++j)
                    v[cc][j] = pok ? ssrc[j * 65536 + px] : 0.0f;
            }
            #pragma unroll
            for (int cc = 0; cc < 3; ++cc) {
                if (cc >= cnt) continue;
                int px = (cbase + cc) * 32 - 1 + lane;
                if (px <= 258) {
                    uint4 pk;
                    pk.x = pack_bf16x2(v[cc][0], v[cc][1]);
                    pk.y = pack_bf16x2(v[cc][2], v[cc][3]);
                    pk.z = pack_bf16x2(v[cc][4], v[cc][5]);
                    pk.w = pack_bf16x2(v[cc][6], v[cc][7]);
                    *reinterpret_cast<uint4*>(smem + SM_A + sslot * AROW + (px + 1) * PXS + sc0 * 2) = pk;
                }
            }
        };

        // acc init = bias (bias add folded into the GEMM)
        float acc[2][8][4];
        #pragma unroll
        for (int mf = 0; mf < 2; ++mf)
            #pragma unroll
            for (int nf = 0; nf < 8; ++nf)
                #pragma unroll
                for (int j = 0; j < 4; ++j)
                    acc[mf][nf][j] = bs[nf * 8 + 2 * cq + (j & 1)];

        #pragma unroll
        for (int t = 0; t < 9; ++t) {
            const int r = t / 3, s = t % 3;
            const int slot = (hrow + 3 + r) & 3;          // row hrow-1+r
            const uint32_t aBase = sb + SM_A + slot * AROW + (pxwbase + s) * PXS + aLane;
            const uint32_t bBase = sb + SM_B + t * 8192;

            if (grpA) tap_mma<true >(acc, aBase, bBase, rowb, colb);
            else      tap_mma<false>(acc, aBase, bBase, rowb, colb);

            // ---- overlap hooks ----
            if (t == 2) BAR_SYNC(1);                 // slot(row hp-1) now dead
            if (t == 5) BAR_SYNC(2);                 // slot(row hp)   now dead
            if (grpA) {                              // stage row hp+3, steps 3..8
                if (t == 3) stage_chunks(0, 2);
                if (t == 4) stage_chunks(2, 2);
                if (t == 5) stage_chunks(4, 2);
                if (t == 6) stage_chunks(6, 1);
                if (t == 7) stage_chunks(7, 1);
                if (t == 8) stage_chunks(8, 1);
            } else {                                 // stage row hp+4, steps 6..8
                if (t == 6) stage_chunks(0, 3);
                if (t == 7) stage_chunks(3, 3);
                if (t == 8) stage_chunks(6, 3);
            }
        }

        // ---- epilogue: min over 64 k (bias already in acc) + tanh + store ----
        #pragma unroll
        for (int mf = 0; mf < 2; ++mf) {
            #pragma unroll
            for (int half = 0; half < 2; ++half) {
                float m = fminf(acc[mf][0][half * 2 + 0], acc[mf][0][half * 2 + 1]);
                #pragma unroll
                for (int nf = 1; nf < 8; ++nf)
                    m = fminf(m, fminf(acc[mf][nf][half * 2 + 0],
                                       acc[mf][nf][half * 2 + 1]));
                m = fminf(m, __shfl_xor_sync(0xFFFFFFFFu, m, 1));
                m = fminf(m, __shfl_xor_sync(0xFFFFFFFFu, m, 2));
                if (cq == 0) {
                    int px = pxwbase + mf * 16 + half * 8 + lrow;
                    out[(size_t)n * 65536 + (size_t)hrow * 256 + px] = tanhf(tanhf(m));
                }
            }
        }

        __syncthreads();   // staged rows visible; all reads done before next writes
    }
}

// ---------------- launch ---------------------------------------------------
extern "C" void kernel_launch(void* const* d_in, const int* in_sizes, int n_in,
                              void* d_out, int out_size) {
    const float* x = (const float*)d_in[0];
    const float* w = (const float*)d_in[1];
    const float* b = (const float*)d_in[2];
    float* out = (float*)d_out;

    cudaFuncSetAttribute(conv_mma_kernel,
                         cudaFuncAttributeMaxDynamicSharedMemorySize, SM_TOTAL);

    prep_w_kernel<<<(9 * 64 * 64 + 255) / 256, 256>>>(w);

    dim3 grid(64, 16);   // (h-strips of 4, n) = 1024 CTAs = 6.92 waves
    conv_mma_kernel<<<grid, 512, SM_TOTAL>>>(x, b, out);
}